// round 1
// baseline (speedup 1.0000x reference)
#include <cuda_runtime.h>
#include <math.h>

// ---------------------------------------------------------------------------
// ShiftedWindowAttention  (B=32, 64x64 grid, C=256, 8 heads x 32, ws=8, shift=4)
//
// Pipeline:
//   K1: qkv[M=131072][768] = gather(x) @ w_qkv^T + b_qkv      (gather = roll+window split)
//   K2: per (window, head): S = q k^T * scale + relpos_bias, shift-mask, softmax, O = S v
//   K3: out = O @ w_out^T + b_out, scattered back (scatter map == gather map by symmetry)
// ---------------------------------------------------------------------------

#define KDIM 256

__device__ float g_qkv[131072 * 768];   // 402.7 MB scratch
__device__ float g_att[131072 * 256];   // 134.2 MB scratch

// roll(-4,-4) + window-split source offset for flattened row gm = win*64 + token.
// Identical map used for the output scatter (roll(+4,+4) after merge cancels).
__device__ __forceinline__ int gather_off(int gm) {
    int w  = gm >> 6;       // global window id (0..2047)
    int t  = gm & 63;       // token in window
    int b  = w >> 6;        // batch
    int wl = w & 63;        // window within image
    int r  = ((wl >> 3) << 3) + (t >> 3);   // rolled-row coordinate
    int c  = ((wl & 7) << 3) + (t & 7);     // rolled-col coordinate
    int sr = (r + 4) & 63;
    int sc = (c + 4) & 63;
    return (b * 4096 + sr * 64 + sc) * KDIM;   // element offset into x / out
}

// ---------------------------------------------------------------------------
// SGEMM: C[128 x (NTILES*64)] = A[128 x 256] @ W^T + bias
// One block owns 128 rows; the full 128x256 A tile is held (transposed) in smem
// so A (= x, gathered) is read from HBM exactly once. W tiles are streamed
// through a double-buffered smem stage (W is small -> L2 resident).
// GATHER_A=true : A gathered via gather_off, C written linearly (K1, qkv)
// GATHER_A=false: A linear (g_att),         C scattered via gather_off (K3)
// ---------------------------------------------------------------------------
template <int NTILES, bool GATHER_A>
__global__ __launch_bounds__(512) void gemm_kernel(
    const float* __restrict__ Ain,   // K1: x       ; K3: unused (g_att)
    const float* __restrict__ W,     // [NTILES*64][256] row-major
    const float* __restrict__ bias,  // [NTILES*64]
    float* __restrict__ Cout)        // K1: unused (g_qkv) ; K3: d_out
{
    constexpr int CSTRIDE = NTILES * 64;
    extern __shared__ float smbuf[];
    float* As = smbuf;                    // [256][132]  (transposed A tile)
    float* Bs = smbuf + 256 * 132;        // [2][16][68] (double-buffered W tile)
    int* aoff = (int*)(smbuf + 256 * 132 + 2 * 16 * 68);  // [128]
    int* coff = aoff + 128;                               // [128]

    const int tid  = threadIdx.x;
    const int row0 = blockIdx.x * 128;

    const float* Aptr = GATHER_A ? Ain : g_att;
    float*       Cptr = GATHER_A ? g_qkv : Cout;

    if (tid < 128) {
        int gm = row0 + tid;
        int g  = gather_off(gm);
        aoff[tid] = GATHER_A ? g : gm * KDIM;
        coff[tid] = GATHER_A ? gm * CSTRIDE : g;
    }
    __syncthreads();

    // Load the full 128x256 A tile, transposed: As[k][m]
    #pragma unroll
    for (int it = 0; it < 16; it++) {
        int idx = it * 512 + tid;       // 0..8191
        int m   = idx >> 6;             // row 0..127
        int k4  = (idx & 63) << 2;      // k 0..252 step 4
        float4 v = *(const float4*)(Aptr + aoff[m] + k4);
        As[(k4 + 0) * 132 + m] = v.x;
        As[(k4 + 1) * 132 + m] = v.y;
        As[(k4 + 2) * 132 + m] = v.z;
        As[(k4 + 3) * 132 + m] = v.w;
    }

    const int m0 = (tid >> 4) * 4;      // 0..124 : this thread's 4 M-rows
    const int n0 = (tid & 15) * 4;      // 0..60  : this thread's 4 N-cols
    const int wn = tid >> 3;            // W loader: n row (0..63)
    const int wk = (tid & 7) * 2;       // W loader: k pair (0..14)

    for (int bn = 0; bn < NTILES; bn++) {
        float acc[4][4];
        #pragma unroll
        for (int i = 0; i < 4; i++)
            #pragma unroll
            for (int j = 0; j < 4; j++) acc[i][j] = 0.f;

        const float* Wb = W + (bn * 64 + wn) * KDIM + wk;

        __syncthreads();                 // all reads of Bs from prev bn done
        {   // stage k-chunk 0
            float2 v = *(const float2*)(Wb);
            Bs[(wk + 0) * 68 + wn] = v.x;
            Bs[(wk + 1) * 68 + wn] = v.y;
        }
        __syncthreads();

        #pragma unroll 1
        for (int kc = 0; kc < 16; kc++) {
            int cur = kc & 1;
            float2 pre;
            if (kc < 15) pre = *(const float2*)(Wb + (kc + 1) * 16);  // prefetch

            #pragma unroll
            for (int k = 0; k < 16; k++) {
                const float4 a = *(const float4*)(As + (kc * 16 + k) * 132 + m0);
                const float4 b = *(const float4*)(Bs + (cur * 16 + k) * 68 + n0);
                acc[0][0] += a.x * b.x; acc[0][1] += a.x * b.y; acc[0][2] += a.x * b.z; acc[0][3] += a.x * b.w;
                acc[1][0] += a.y * b.x; acc[1][1] += a.y * b.y; acc[1][2] += a.y * b.z; acc[1][3] += a.y * b.w;
                acc[2][0] += a.z * b.x; acc[2][1] += a.z * b.y; acc[2][2] += a.z * b.z; acc[2][3] += a.z * b.w;
                acc[3][0] += a.w * b.x; acc[3][1] += a.w * b.y; acc[3][2] += a.w * b.z; acc[3][3] += a.w * b.w;
            }
            if (kc < 15) {
                __syncthreads();
                int nb = (cur ^ 1) * 16;
                Bs[(nb + wk + 0) * 68 + wn] = pre.x;
                Bs[(nb + wk + 1) * 68 + wn] = pre.y;
                __syncthreads();
            }
        }

        // epilogue: add bias, store
        float b0 = bias[bn * 64 + n0 + 0];
        float b1 = bias[bn * 64 + n0 + 1];
        float b2 = bias[bn * 64 + n0 + 2];
        float b3 = bias[bn * 64 + n0 + 3];
        #pragma unroll
        for (int i = 0; i < 4; i++) {
            float4 o;
            o.x = acc[i][0] + b0;
            o.y = acc[i][1] + b1;
            o.z = acc[i][2] + b2;
            o.w = acc[i][3] + b3;
            *(float4*)(Cptr + coff[m0 + i] + bn * 64 + n0) = o;
        }
    }
}

// ---------------------------------------------------------------------------
// Attention: one block per (window, head). 128 threads (4 warps), warp owns
// 16 query rows; lane covers key columns {lane, lane+32} / head-dim lane.
// Bias = pos_enc[h][(yi-yj+7)*15 + (xi-xj+7)]; shift mask from region ids.
// ---------------------------------------------------------------------------
__global__ __launch_bounds__(128) void attn_kernel(const float* __restrict__ pos_enc)
{
    __shared__ float qs[64][33];
    __shared__ float kT[32][65];
    __shared__ float vs[64][33];
    __shared__ float S[64][65];
    __shared__ float pe[225];
    __shared__ int   rg[64];

    const int w    = blockIdx.x;       // window 0..2047
    const int h    = blockIdx.y;       // head 0..7
    const int tid  = threadIdx.x;
    const int lane = tid & 31;
    const int warp = tid >> 5;
    const float SCALE = 0.17677669529663687f;   // 32^-0.5

    const float* base = g_qkv + (size_t)w * (64 * 768) + h * 32;

    for (int idx = tid; idx < 2048; idx += 128) {
        int i = idx >> 5, d = idx & 31;
        qs[i][d] = base[i * 768 + d] * SCALE;
        kT[d][i] = base[i * 768 + 256 + d];
        vs[i][d] = base[i * 768 + 512 + d];
    }
    for (int idx = tid; idx < 225; idx += 128) pe[idx] = pos_enc[h * 225 + idx];
    if (tid < 64) {
        int wl = w & 63;
        int r  = ((wl >> 3) << 3) + (tid >> 3);
        int c  = ((wl & 7) << 3) + (tid & 7);
        int rr = (r < 56) ? 0 : ((r < 60) ? 1 : 2);
        int cc = (c < 56) ? 0 : ((c < 60) ? 1 : 2);
        rg[tid] = rr * 3 + cc;
    }
    __syncthreads();

    // S = q k^T + bias, mask, softmax  (4-row register blocking)
    for (int i0 = warp * 16; i0 < warp * 16 + 16; i0 += 4) {
        float a0[4] = {0, 0, 0, 0}, a1[4] = {0, 0, 0, 0};
        #pragma unroll
        for (int d = 0; d < 32; d++) {
            float k0 = kT[d][lane];
            float k1 = kT[d][lane + 32];
            #pragma unroll
            for (int r = 0; r < 4; r++) {
                float qv = qs[i0 + r][d];
                a0[r] += qv * k0;
                a1[r] += qv * k1;
            }
        }
        #pragma unroll
        for (int r = 0; r < 4; r++) {
            int i = i0 + r;
            int yi = i >> 3, xi = i & 7, ri = rg[i];
            int j0 = lane, j1 = lane + 32;
            float s0 = a0[r] + pe[(yi - (j0 >> 3) + 7) * 15 + (xi - (j0 & 7) + 7)];
            float s1 = a1[r] + pe[(yi - (j1 >> 3) + 7) * 15 + (xi - (j1 & 7) + 7)];
            if (rg[j0] != ri) s0 = -INFINITY;
            if (rg[j1] != ri) s1 = -INFINITY;
            float mx = fmaxf(s0, s1);
            #pragma unroll
            for (int o = 16; o > 0; o >>= 1) mx = fmaxf(mx, __shfl_xor_sync(0xffffffffu, mx, o));
            float e0 = __expf(s0 - mx);
            float e1 = __expf(s1 - mx);
            float sm = e0 + e1;
            #pragma unroll
            for (int o = 16; o > 0; o >>= 1) sm += __shfl_xor_sync(0xffffffffu, sm, o);
            float inv = 1.0f / sm;
            S[i][j0] = e0 * inv;
            S[i][j1] = e1 * inv;
        }
    }
    __syncthreads();

    // O = S v
    size_t obase = (size_t)w * (64 * 256) + h * 32 + lane;
    for (int i0 = warp * 16; i0 < warp * 16 + 16; i0 += 4) {
        float acc[4] = {0, 0, 0, 0};
        #pragma unroll
        for (int j = 0; j < 64; j++) {
            float vv = vs[j][lane];
            #pragma unroll
            for (int r = 0; r < 4; r++) acc[r] += S[i0 + r][j] * vv;
        }
        #pragma unroll
        for (int r = 0; r < 4; r++) g_att[obase + (size_t)(i0 + r) * 256] = acc[r];
    }
}

// ---------------------------------------------------------------------------
extern "C" void kernel_launch(void* const* d_in, const int* in_sizes, int n_in,
                              void* d_out, int out_size)
{
    const float* x     = (const float*)d_in[0];
    const float* w_qkv = (const float*)d_in[1];
    const float* b_qkv = (const float*)d_in[2];
    const float* w_out = (const float*)d_in[3];
    const float* b_out = (const float*)d_in[4];
    const float* pos   = (const float*)d_in[5];
    float* out = (float*)d_out;

    const int SMEM = (256 * 132 + 2 * 16 * 68) * 4 + 256 * 4;   // 144,896 B

    cudaFuncSetAttribute(gemm_kernel<12, true>,
                         cudaFuncAttributeMaxDynamicSharedMemorySize, SMEM);
    cudaFuncSetAttribute(gemm_kernel<4, false>,
                         cudaFuncAttributeMaxDynamicSharedMemorySize, SMEM);

    // K1: gather + QKV projection
    gemm_kernel<12, true><<<1024, 512, SMEM>>>(x, w_qkv, b_qkv, nullptr);
    // K2: windowed attention
    attn_kernel<<<dim3(2048, 8), 128>>>(pos);
    // K3: output projection + scatter
    gemm_kernel<4, false><<<1024, 512, SMEM>>>(nullptr, w_out, b_out, out);
}

// round 3
// speedup vs baseline: 3.6391x; 3.6391x over previous
#include <cuda_runtime.h>
#include <cuda_bf16.h>
#include <math.h>
#include <stdint.h>

// ---------------------------------------------------------------------------
// ShiftedWindowAttention (B=32, 64x64, C=256, 8 heads x 32, ws=8, shift=4)
//
// tcgen05 is NOT available (harness ptxas target = sm_103, no 'a' feature).
// GEMMs use classic mma.sync bf16 (HMMA) with split-bf16 (bf16x3) emulation:
//   x = hi + lo (bf16 each); x*y ~= hiA*hiB + loA*hiB + hiA*loB  (err ~1e-5)
//
// K0: convert x (gathered) / w_qkv / w_out  -> split bf16 [hi(256)|lo(256)]
// K1: mma.sync GEMM  g_qkv[131072][768] = x2 @ w2^T + b_qkv   (K''=768)
// K2: windowed attention (FFMA), writes g_att2 split bf16
// K3: mma.sync GEMM  out = att2 @ w3^T + b_out, rows scattered (inverse roll)
// ---------------------------------------------------------------------------

#define KDIM 256
typedef __nv_bfloat16 bf16;

__device__ float g_qkv [131072UL * 768];   // f32 qkv (read by attention)
__device__ bf16  g_x2  [131072UL * 512];   // x gathered, [hi|lo]
__device__ bf16  g_att2[131072UL * 512];   // attention out, [hi|lo]
__device__ bf16  g_w2  [768 * 512];        // w_qkv split
__device__ bf16  g_w3  [256 * 512];        // w_out split

// roll(-4,-4) + window-split source offset for row gm = win*64 + token.
// Same map serves the output scatter (roll(+4,+4) after merge cancels).
__device__ __forceinline__ int gather_off(int gm) {
    int w  = gm >> 6;
    int t  = gm & 63;
    int b  = w >> 6;
    int wl = w & 63;
    int r  = ((wl >> 3) << 3) + (t >> 3);
    int c  = ((wl & 7) << 3) + (t & 7);
    int sr = (r + 4) & 63;
    int sc = (c + 4) & 63;
    return (b * 4096 + sr * 64 + sc) * KDIM;
}

#define SWZ(off) ((off) ^ (((off) >> 3) & 0x70))

__device__ __forceinline__ uint32_t smem_u32(const void* p) {
    uint32_t a;
    asm("{ .reg .u64 t; cvta.to.shared.u64 t, %1; cvt.u32.u64 %0, t; }"
        : "=r"(a) : "l"(p));
    return a;
}

// ---------------------------------------------------------------------------
// K0: split-bf16 conversion. mode 0: x (gathered) -> g_x2
//                            mode 1: w_qkv -> g_w2,  mode 2: w_out -> g_w3
// ---------------------------------------------------------------------------
__global__ void convert_kernel(const float* __restrict__ src, int nrows, int mode)
{
    int idx = blockIdx.x * blockDim.x + threadIdx.x;
    if (idx >= nrows * 64) return;
    int row = idx >> 6;
    int c   = (idx & 63) << 2;
    const float* sp = src + (mode == 0 ? gather_off(row) : row * 256) + c;
    float4 v = *(const float4*)sp;
    bf16* dst = (mode == 0) ? g_x2 : ((mode == 1) ? g_w2 : g_w3);

    float vs[4] = {v.x, v.y, v.z, v.w};
    bf16 __align__(8) hi[4];
    bf16 __align__(8) lo[4];
    #pragma unroll
    for (int i = 0; i < 4; i++) {
        hi[i] = __float2bfloat16(vs[i]);
        lo[i] = __float2bfloat16(vs[i] - __bfloat162float(hi[i]));
    }
    *(uint2*)(dst + (size_t)row * 512 + c)       = *(uint2*)hi;
    *(uint2*)(dst + (size_t)row * 512 + 256 + c) = *(uint2*)lo;
}

// ---------------------------------------------------------------------------
// mma.sync GEMM.  C[128 x 128] per CTA.  8 warps (2 x 4), warp tile 64x32.
// K'' = 768 = 3 segments x 256; K-chunk = 64 bf16 (128 B rows, SW128 swizzle).
// A, B staged via double-buffered cp.async.  grid = (NT n-tiles, 1024 m-tiles)
// with n fastest so one A tile's n-tiles share L2.
// ---------------------------------------------------------------------------
template <int NT, bool SCATTER>
__global__ __launch_bounds__(256, 2) void mma_gemm(const float* __restrict__ bias,
                                                   float* __restrict__ Cout)
{
    extern __shared__ __align__(1024) char smem[];
    const bf16* Ag = SCATTER ? g_att2 : g_x2;
    const bf16* Bg = SCATTER ? g_w3   : g_w2;
    float* C = SCATTER ? Cout : g_qkv;
    constexpr int CSTRIDE = NT * 128;

    const int tid  = threadIdx.x;
    const int lane = tid & 31;
    const int warp = tid >> 5;
    const int m0   = blockIdx.y * 128;
    const int n0c  = blockIdx.x * 128;
    const uint32_t sbase = smem_u32(smem);

    // stage chunk c (0..11) into buffer buf. chunk -> gmem cols:
    //   seg = c/4 : 0 -> hiA*hiB, 1 -> loA*hiB, 2 -> hiA*loB
    auto stage = [&](int c, int buf) {
        int seg = c >> 2, kin = (c & 3) * 64;
        int acol = (seg == 1 ? 256 : 0) + kin;
        int bcol = (seg == 2 ? 256 : 0) + kin;
        uint32_t ab = sbase + buf * 32768;
        uint32_t bb = ab + 16384;
        #pragma unroll
        for (int i = 0; i < 4; i++) {
            int idx = tid + i * 256;
            int r  = idx >> 3;
            int ch = idx & 7;
            uint32_t off = (uint32_t)(r * 128 + ch * 16);
            const bf16* as = Ag + (size_t)(m0 + r) * 512 + acol + ch * 8;
            const bf16* bs = Bg + (size_t)(n0c + r) * 512 + bcol + ch * 8;
            asm volatile("cp.async.cg.shared.global [%0], [%1], 16;"
                         :: "r"(ab + SWZ(off)), "l"(as));
            asm volatile("cp.async.cg.shared.global [%0], [%1], 16;"
                         :: "r"(bb + SWZ(off)), "l"(bs));
        }
        asm volatile("cp.async.commit_group;");
    };

    float d[4][4][4];
    #pragma unroll
    for (int mt = 0; mt < 4; mt++)
        #pragma unroll
        for (int nt = 0; nt < 4; nt++)
            #pragma unroll
            for (int j = 0; j < 4; j++) d[mt][nt][j] = 0.f;

    const int wm0 = (warp >> 2) * 64;   // warp m offset in CTA tile
    const int wn0 = (warp & 3) * 32;    // warp n offset

    stage(0, 0);
    for (int c = 0; c < 12; c++) {
        if (c < 11) {
            stage(c + 1, (c + 1) & 1);
            asm volatile("cp.async.wait_group 1;");
        } else {
            asm volatile("cp.async.wait_group 0;");
        }
        __syncthreads();

        uint32_t ab = sbase + (c & 1) * 32768;
        uint32_t bb = ab + 16384;

        #pragma unroll
        for (int ks = 0; ks < 4; ks++) {
            uint32_t a[4][4], b[4][2];
            #pragma unroll
            for (int mt = 0; mt < 4; mt++) {
                int row = wm0 + mt * 16 + (lane & 15);
                int col = ks * 16 + ((lane >> 1) & 8);
                uint32_t off = (uint32_t)(row * 128 + col * 2);
                asm volatile(
                    "ldmatrix.sync.aligned.m8n8.x4.shared.b16 {%0,%1,%2,%3}, [%4];"
                    : "=r"(a[mt][0]), "=r"(a[mt][1]), "=r"(a[mt][2]), "=r"(a[mt][3])
                    : "r"(ab + SWZ(off)));
            }
            #pragma unroll
            for (int np = 0; np < 2; np++) {
                int row = wn0 + np * 16 + (lane & 7) + ((lane & 16) ? 8 : 0);
                int col = ks * 16 + ((lane & 8) ? 8 : 0);
                uint32_t off = (uint32_t)(row * 128 + col * 2);
                asm volatile(
                    "ldmatrix.sync.aligned.m8n8.x4.shared.b16 {%0,%1,%2,%3}, [%4];"
                    : "=r"(b[2 * np][0]), "=r"(b[2 * np][1]),
                      "=r"(b[2 * np + 1][0]), "=r"(b[2 * np + 1][1])
                    : "r"(bb + SWZ(off)));
            }
            #pragma unroll
            for (int mt = 0; mt < 4; mt++)
                #pragma unroll
                for (int nt = 0; nt < 4; nt++)
                    asm volatile(
                        "mma.sync.aligned.m16n8k16.row.col.f32.bf16.bf16.f32 "
                        "{%0,%1,%2,%3}, {%4,%5,%6,%7}, {%8,%9}, {%0,%1,%2,%3};"
                        : "+f"(d[mt][nt][0]), "+f"(d[mt][nt][1]),
                          "+f"(d[mt][nt][2]), "+f"(d[mt][nt][3])
                        : "r"(a[mt][0]), "r"(a[mt][1]), "r"(a[mt][2]), "r"(a[mt][3]),
                          "r"(b[nt][0]), "r"(b[nt][1]));
        }
        if (c < 11) __syncthreads();
    }

    // epilogue: bias add + store (row scatter for K3)
    const int cc0 = n0c + wn0 + (lane & 3) * 2;
    #pragma unroll
    for (int mt = 0; mt < 4; mt++) {
        int grow = m0 + wm0 + mt * 16 + (lane >> 2);
        size_t ob0 = SCATTER ? (size_t)gather_off(grow)     : (size_t)grow * CSTRIDE;
        size_t ob1 = SCATTER ? (size_t)gather_off(grow + 8) : (size_t)(grow + 8) * CSTRIDE;
        #pragma unroll
        for (int nt = 0; nt < 4; nt++) {
            int col = cc0 + nt * 8;
            float bx = bias[col], by = bias[col + 1];
            float2 o0 = {d[mt][nt][0] + bx, d[mt][nt][1] + by};
            float2 o1 = {d[mt][nt][2] + bx, d[mt][nt][3] + by};
            *(float2*)(C + ob0 + col) = o0;
            *(float2*)(C + ob1 + col) = o1;
        }
    }
}

// ---------------------------------------------------------------------------
// K2: windowed attention (unchanged compute; epilogue writes split bf16)
// ---------------------------------------------------------------------------
__global__ __launch_bounds__(128) void attn_kernel(const float* __restrict__ pos_enc)
{
    __shared__ float qs[64][33];
    __shared__ float kT[32][65];
    __shared__ float vs[64][33];
    __shared__ float S[64][65];
    __shared__ float pe[225];
    __shared__ int   rg[64];

    const int w    = blockIdx.x;
    const int h    = blockIdx.y;
    const int tid  = threadIdx.x;
    const int lane = tid & 31;
    const int warp = tid >> 5;
    const float SCALE = 0.17677669529663687f;

    const float* base = g_qkv + (size_t)w * (64 * 768) + h * 32;

    for (int idx = tid; idx < 2048; idx += 128) {
        int i = idx >> 5, d = idx & 31;
        qs[i][d] = base[i * 768 + d] * SCALE;
        kT[d][i] = base[i * 768 + 256 + d];
        vs[i][d] = base[i * 768 + 512 + d];
    }
    for (int idx = tid; idx < 225; idx += 128) pe[idx] = pos_enc[h * 225 + idx];
    if (tid < 64) {
        int wl = w & 63;
        int r  = ((wl >> 3) << 3) + (tid >> 3);
        int c  = ((wl & 7) << 3) + (tid & 7);
        int rr = (r < 56) ? 0 : ((r < 60) ? 1 : 2);
        int cc = (c < 56) ? 0 : ((c < 60) ? 1 : 2);
        rg[tid] = rr * 3 + cc;
    }
    __syncthreads();

    for (int i0 = warp * 16; i0 < warp * 16 + 16; i0 += 4) {
        float a0[4] = {0, 0, 0, 0}, a1[4] = {0, 0, 0, 0};
        #pragma unroll
        for (int d = 0; d < 32; d++) {
            float k0 = kT[d][lane];
            float k1 = kT[d][lane + 32];
            #pragma unroll
            for (int r = 0; r < 4; r++) {
                float qv = qs[i0 + r][d];
                a0[r] += qv * k0;
                a1[r] += qv * k1;
            }
        }
        #pragma unroll
        for (int r = 0; r < 4; r++) {
            int i = i0 + r;
            int yi = i >> 3, xi = i & 7, ri = rg[i];
            int j0 = lane, j1 = lane + 32;
            float s0 = a0[r] + pe[(yi - (j0 >> 3) + 7) * 15 + (xi - (j0 & 7) + 7)];
            float s1 = a1[r] + pe[(yi - (j1 >> 3) + 7) * 15 + (xi - (j1 & 7) + 7)];
            if (rg[j0] != ri) s0 = -INFINITY;
            if (rg[j1] != ri) s1 = -INFINITY;
            float mx = fmaxf(s0, s1);
            #pragma unroll
            for (int o = 16; o > 0; o >>= 1) mx = fmaxf(mx, __shfl_xor_sync(0xffffffffu, mx, o));
            float e0 = __expf(s0 - mx);
            float e1 = __expf(s1 - mx);
            float sm = e0 + e1;
            #pragma unroll
            for (int o = 16; o > 0; o >>= 1) sm += __shfl_xor_sync(0xffffffffu, sm, o);
            float inv = 1.0f / sm;
            S[i][j0] = e0 * inv;
            S[i][j1] = e1 * inv;
        }
    }
    __syncthreads();

    // O = S v, write split bf16 to g_att2
    size_t obase = (size_t)(w * 64) * 512 + h * 32 + lane;
    for (int i0 = warp * 16; i0 < warp * 16 + 16; i0 += 4) {
        float acc[4] = {0, 0, 0, 0};
        #pragma unroll
        for (int j = 0; j < 64; j++) {
            float vv = vs[j][lane];
            #pragma unroll
            for (int r = 0; r < 4; r++) acc[r] += S[i0 + r][j] * vv;
        }
        #pragma unroll
        for (int r = 0; r < 4; r++) {
            float vacc = acc[r];
            bf16 hb = __float2bfloat16(vacc);
            bf16 lb = __float2bfloat16(vacc - __bfloat162float(hb));
            size_t ro = obase + (size_t)(i0 + r) * 512;
            g_att2[ro]       = hb;
            g_att2[ro + 256] = lb;
        }
    }
}

// ---------------------------------------------------------------------------
extern "C" void kernel_launch(void* const* d_in, const int* in_sizes, int n_in,
                              void* d_out, int out_size)
{
    const float* x     = (const float*)d_in[0];
    const float* w_qkv = (const float*)d_in[1];
    const float* b_qkv = (const float*)d_in[2];
    const float* w_out = (const float*)d_in[3];
    const float* b_out = (const float*)d_in[4];
    const float* pos   = (const float*)d_in[5];
    float* out = (float*)d_out;

    const int SMEM = 65536;
    cudaFuncSetAttribute(mma_gemm<6, false>,
                         cudaFuncAttributeMaxDynamicSharedMemorySize, SMEM);
    cudaFuncSetAttribute(mma_gemm<2, true>,
                         cudaFuncAttributeMaxDynamicSharedMemorySize, SMEM);

    // K0: conversions
    convert_kernel<<<32768, 256>>>(x, 131072, 0);
    convert_kernel<<<192,   256>>>(w_qkv, 768, 1);
    convert_kernel<<<64,    256>>>(w_out, 256, 2);
    // K1: QKV projection (HMMA, bf16x3)
    mma_gemm<6, false><<<dim3(6, 1024), 256, SMEM>>>(b_qkv, nullptr);
    // K2: windowed attention
    attn_kernel<<<dim3(2048, 8), 128>>>(pos);
    // K3: output projection + scatter (HMMA, bf16x3)
    mma_gemm<2, true><<<dim3(2, 1024), 256, SMEM>>>(b_out, out);
}